// round 9
// baseline (speedup 1.0000x reference)
#include <cuda_runtime.h>

#define MAXR 100.0f

__device__ __forceinline__ float tanh_fast(float x) {
    float r;
    asm("tanh.approx.f32 %0, %1;" : "=f"(r) : "f"(x));
    return r;
}

// Accurate-enough fast tanh: 1 - 2/(1+e^{2s}).  ~1e-7 abs err, ~5 inst.
__device__ __forceinline__ float tanh_exp(float s) {
    float e2 = __expf(2.0f * s);
    return 1.0f - __fdividef(2.0f, 1.0f + e2);
}

// ---------------------------------------------------------------------------
// Fused kernel, per block = 16 consecutive same-row pixels, 256 threads =
// 8 warps, each warp owns TWO adjacent pixels (weight + window sharing):
//   per thread conv: 18 weight LDS.64 + 12 tile LDS + 72 FMA for 2 pixels
//   (vs 72 weight + 36 tile LDS for the same 2 pixels in the 1-px/warp form).
// Weights stored as float2 (o0,o1) pairs: sw2[c*9+tap] = (w0, w1).
// Screen C0: logit_j = -|a|*mean_i(|d|*tanh(|a d|)) <= 0 clipped at -100;
//   |a|*(|b|*mean|x| - max|x|) >= 101 ==> all logits clip -> softmax uniform
//   -> out = mean_c(x). Fallback: exact tanh path (rare).
// ---------------------------------------------------------------------------
__global__ __launch_bounds__(256, 6) void dsf_fused_kernel(
    const float* __restrict__ x,
    const float* __restrict__ wgt,
    const float* __restrict__ bias,
    float* __restrict__ out) {

    __shared__ float  tile[64][57];  // [c][r*18+cc]; 57 coprime 32
    __shared__ float2 sw2[576];      // (w_out0, w_out1) for [c][tap]

    int tid = threadIdx.x;
    int p0  = blockIdx.x * 16;
    int b   = p0 >> 12;
    int hw0 = p0 & 4095;
    int h   = hw0 >> 6;
    int w0  = hw0 & 63;              // multiple of 16 -> float4 aligned
    const float* xb = x + b * 262144;

    // ---- Phase 1a: halo tile, 768 items = (c, r, f), 3 per thread ---------
    #pragma unroll
    for (int k = 0; k < 3; k++) {
        int q  = tid + k * 256;       // 0..767
        int c  = q / 12;
        int rm = q - c * 12;
        int r  = rm >> 2;
        int f  = rm & 3;
        int hh = h + r - 1;
        bool rowok = (unsigned)hh < 64u;
        const float* src = xb + c * 4096 + hh * 64;

        float4 v = make_float4(0.f, 0.f, 0.f, 0.f);
        if (rowok)
            v = *reinterpret_cast<const float4*>(src + w0 + f * 4);
        float* d = &tile[c][r * 18 + 1 + f * 4];
        d[0] = v.x; d[1] = v.y; d[2] = v.z; d[3] = v.w;

        if (f == 0) {
            float hv = 0.0f;
            if (rowok && w0 > 0) hv = src[w0 - 1];
            tile[c][r * 18] = hv;
        } else if (f == 3) {
            float hv = 0.0f;
            if (rowok && w0 + 16 < 64) hv = src[w0 + 16];
            tile[c][r * 18 + 17] = hv;
        }
    }
    // ---- Phase 1b: weights -> (o0,o1) float2 pairs, trivial indexing ------
    if (tid < 144) {
        const float4* gw = reinterpret_cast<const float4*>(wgt);
        float4 wa = gw[tid];          // out0 floats [4t..4t+3]
        float4 wb = gw[144 + tid];    // out1 floats [576+4t..576+4t+3]
        int e = tid * 4;
        sw2[e + 0] = make_float2(wa.x, wb.x);
        sw2[e + 1] = make_float2(wa.y, wb.y);
        sw2[e + 2] = make_float2(wa.z, wb.z);
        sw2[e + 3] = make_float2(wa.w, wb.w);
    }
    float b0 = __ldg(&bias[0]);
    float b1 = __ldg(&bias[1]);
    __syncthreads();

    int wid  = tid >> 5;             // warp 0..7 -> pixels 2w, 2w+1
    int lane = tid & 31;
    int px0  = wid * 2;
    int px1  = px0 + 1;

    // ---- Phase 2: conv for BOTH pixels, shared window + shared weights ----
    float cA0 = 0.f, cA1 = 0.f;      // pixel0: out0, out1
    float cB0 = 0.f, cB1 = 0.f;      // pixel1: out0, out1
    #pragma unroll
    for (int g = 0; g < 2; g++) {
        int c = lane + g * 32;
        const float*  t = &tile[c][0];
        const float2* W = &sw2[c * 9];
        #pragma unroll
        for (int r = 0; r < 3; r++) {
            float v0 = t[r * 18 + px0];
            float v1 = t[r * 18 + px0 + 1];
            float v2 = t[r * 18 + px0 + 2];
            float v3 = t[r * 18 + px0 + 3];
            float2 W0 = W[r * 3 + 0];
            float2 W1 = W[r * 3 + 1];
            float2 W2 = W[r * 3 + 2];
            cA0 = fmaf(v0, W0.x, cA0);  cA1 = fmaf(v0, W0.y, cA1);
            cA0 = fmaf(v1, W1.x, cA0);  cA1 = fmaf(v1, W1.y, cA1);
            cA0 = fmaf(v2, W2.x, cA0);  cA1 = fmaf(v2, W2.y, cA1);
            cB0 = fmaf(v1, W0.x, cB0);  cB1 = fmaf(v1, W0.y, cB1);
            cB0 = fmaf(v2, W1.x, cB0);  cB1 = fmaf(v2, W1.y, cB1);
            cB0 = fmaf(v3, W2.x, cB0);  cB1 = fmaf(v3, W2.y, cB1);
        }
    }

    // ---- Channel values + one fused 10-value butterfly --------------------
    float xa0 = tile[lane][19 + px0];
    float xa1 = tile[lane + 32][19 + px0];
    float xb0 = tile[lane][19 + px1];
    float xb1 = tile[lane + 32][19 + px1];

    float ssA = xa0 + xa1;
    float saA = fabsf(xa0) + fabsf(xa1);
    float smA = fmaxf(fabsf(xa0), fabsf(xa1));
    float ssB = xb0 + xb1;
    float saB = fabsf(xb0) + fabsf(xb1);
    float smB = fmaxf(fabsf(xb0), fabsf(xb1));
    #pragma unroll
    for (int o = 16; o > 0; o >>= 1) {
        cA0 += __shfl_xor_sync(0xffffffffu, cA0, o);
        cA1 += __shfl_xor_sync(0xffffffffu, cA1, o);
        cB0 += __shfl_xor_sync(0xffffffffu, cB0, o);
        cB1 += __shfl_xor_sync(0xffffffffu, cB1, o);
        ssA += __shfl_xor_sync(0xffffffffu, ssA, o);
        saA += __shfl_xor_sync(0xffffffffu, saA, o);
        smA  = fmaxf(smA, __shfl_xor_sync(0xffffffffu, smA, o));
        ssB += __shfl_xor_sync(0xffffffffu, ssB, o);
        saB += __shfl_xor_sync(0xffffffffu, saB, o);
        smB  = fmaxf(smB, __shfl_xor_sync(0xffffffffu, smB, o));
    }

    float alA = MAXR * tanh_exp(cA0 + b0);
    float beA = MAXR * tanh_exp(cA1 + b1);
    float alB = MAXR * tanh_exp(cB0 + b0);
    float beB = MAXR * tanh_exp(cB1 + b1);

    // ---- Screen C0 per pixel ----------------------------------------------
    bool okA = fabsf(alA) * (fabsf(beA) * (saA * (1.0f / 64.0f)) - smA) >= 101.0f;
    bool okB = fabsf(alB) * (fabsf(beB) * (saB * (1.0f / 64.0f)) - smB) >= 101.0f;
    if (lane == 0) {
        if (okA) out[p0 + px0] = ssA * (1.0f / 64.0f);
        if (okB) out[p0 + px1] = ssB * (1.0f / 64.0f);
    }
    if (okA && okB) return;

    // ---- Exact path(s) (rare): full tanh interaction + softmax ------------
    #pragma unroll
    for (int p = 0; p < 2; p++) {
        bool ok      = p ? okB : okA;
        if (ok) continue;
        float alpha  = p ? alB : alA;
        float beta   = p ? beB : beA;
        float xj0    = p ? xb0 : xa0;
        float xj1    = p ? xb1 : xa1;
        int   px     = p ? px1 : px0;

        float ab  = alpha * beta;
        float nc0 = -alpha * xj0;
        float nc1 = -alpha * xj1;
        const float* xc = &tile[0][19 + px];

        float acc0 = 0.0f, acc1 = 0.0f;
        #pragma unroll 8
        for (int i = 0; i < 64; i++) {
            float xi = xc[i * 57];      // LDS broadcast
            float z0 = fmaf(ab, xi, nc0);
            float z1 = fmaf(ab, xi, nc1);
            acc0 = fmaf(z0, tanh_fast(z0), acc0);
            acc1 = fmaf(z1, tanh_fast(z1), acc1);
        }

        float l0 = fminf(fmaxf(acc0 * (-1.0f / 64.0f), -MAXR), MAXR);
        float l1 = fminf(fmaxf(acc1 * (-1.0f / 64.0f), -MAXR), MAXR);

        float m = fmaxf(l0, l1);
        #pragma unroll
        for (int o = 16; o > 0; o >>= 1)
            m = fmaxf(m, __shfl_xor_sync(0xffffffffu, m, o));

        float e0 = __expf(l0 - m);
        float e1 = __expf(l1 - m);
        float num = fmaf(xj0, e0, xj1 * e1);
        float den = e0 + e1;
        #pragma unroll
        for (int o = 16; o > 0; o >>= 1) {
            num += __shfl_xor_sync(0xffffffffu, num, o);
            den += __shfl_xor_sync(0xffffffffu, den, o);
        }

        if (lane == 0) out[p0 + px] = num / den;
    }
}

extern "C" void kernel_launch(void* const* d_in, const int* in_sizes, int n_in,
                              void* d_out, int out_size) {
    const float* x    = (const float*)d_in[0];
    const float* w    = (const float*)d_in[1];
    const float* bias = (const float*)d_in[2];
    float* out        = (float*)d_out;

    dsf_fused_kernel<<<1024, 256>>>(x, w, bias, out);
}

// round 10
// speedup vs baseline: 1.1404x; 1.1404x over previous
#include <cuda_runtime.h>

#define MAXR 100.0f

__device__ __forceinline__ float tanh_fast(float x) {
    float r;
    asm("tanh.approx.f32 %0, %1;" : "=f"(r) : "f"(x));
    return r;
}

// Accurate-enough fast tanh: 1 - 2/(1+e^{2s}).  ~1e-7 abs err, ~5 inst.
__device__ __forceinline__ float tanh_exp(float s) {
    float e2 = __expf(2.0f * s);
    return 1.0f - __fdividef(2.0f, 1.0f + e2);
}

// ---------------------------------------------------------------------------
// Fused kernel, per block = 32 consecutive same-row pixels (half image row).
// 512 threads = 16 warps, each warp owns TWO adjacent pixels.
// Grid = 512 blocks -> fits ONE wave at occupancy 4 (148*4 = 592 slots),
// eliminating the 2-wave quantization that pinned R6-R9 at ~15.5us.
// Weights (1152 floats) loaded once per block, amortized over 32 pixels.
// Screen C0: logit_j = -|a|*mean_i(|d|*tanh(|a d|)) <= 0 clipped at -100;
//   |a|*(|b|*mean|x| - max|x|) >= 101 ==> all logits clip -> softmax uniform
//   -> out = mean_c(x). Fallback: exact tanh path (rare).
// ---------------------------------------------------------------------------
__global__ __launch_bounds__(512, 4) void dsf_fused_kernel(
    const float* __restrict__ x,
    const float* __restrict__ wgt,
    const float* __restrict__ bias,
    float* __restrict__ out) {

    __shared__ float  tile[64][105]; // [c][r*35+cc]; 105%32=9 coprime -> ok
    __shared__ float2 sw2[576];      // (w_out0, w_out1) for [c][tap]

    int tid = threadIdx.x;
    int p0  = blockIdx.x * 32;
    int b   = p0 >> 12;
    int hw0 = p0 & 4095;
    int h   = hw0 >> 6;
    int w0  = hw0 & 63;              // 0 or 32 -> float4 aligned
    const float* xb = x + b * 262144;

    // ---- Phase 1a: halo tile, 1536 items = (c, r, f), exactly 3/thread ----
    #pragma unroll
    for (int k = 0; k < 3; k++) {
        int q  = tid + k * 512;       // 0..1535, no guard needed
        int c  = q / 24;
        int rm = q - c * 24;
        int r  = rm >> 3;
        int f  = rm & 7;
        int hh = h + r - 1;
        bool rowok = (unsigned)hh < 64u;
        const float* src = xb + c * 4096 + hh * 64;

        float4 v = make_float4(0.f, 0.f, 0.f, 0.f);
        if (rowok)
            v = *reinterpret_cast<const float4*>(src + w0 + f * 4);
        float* d = &tile[c][r * 35 + 1 + f * 4];
        d[0] = v.x; d[1] = v.y; d[2] = v.z; d[3] = v.w;

        if (f == 0) {
            float hv = 0.0f;
            if (rowok && w0 > 0) hv = src[w0 - 1];
            tile[c][r * 35] = hv;
        } else if (f == 7) {
            float hv = 0.0f;
            if (rowok && w0 + 32 < 64) hv = src[w0 + 32];
            tile[c][r * 35 + 33] = hv;
        }
    }
    // ---- Phase 1b: weights -> (o0,o1) float2 pairs, trivial indexing ------
    if (tid < 144) {
        const float4* gw = reinterpret_cast<const float4*>(wgt);
        float4 wa = gw[tid];          // out0 floats [4t..4t+3]
        float4 wb = gw[144 + tid];    // out1 floats [576+4t..576+4t+3]
        int e = tid * 4;
        sw2[e + 0] = make_float2(wa.x, wb.x);
        sw2[e + 1] = make_float2(wa.y, wb.y);
        sw2[e + 2] = make_float2(wa.z, wb.z);
        sw2[e + 3] = make_float2(wa.w, wb.w);
    }
    float b0 = __ldg(&bias[0]);
    float b1 = __ldg(&bias[1]);
    __syncthreads();

    int wid  = tid >> 5;             // warp 0..15 -> pixels 2w, 2w+1
    int lane = tid & 31;
    int px0  = wid * 2;
    int px1  = px0 + 1;

    // ---- Phase 2: conv for BOTH pixels, shared window + shared weights ----
    float cA0 = 0.f, cA1 = 0.f;      // pixel0: out0, out1
    float cB0 = 0.f, cB1 = 0.f;      // pixel1: out0, out1
    #pragma unroll
    for (int g = 0; g < 2; g++) {
        int c = lane + g * 32;
        const float*  t = &tile[c][0];
        const float2* W = &sw2[c * 9];
        #pragma unroll
        for (int r = 0; r < 3; r++) {
            float v0 = t[r * 35 + px0];
            float v1 = t[r * 35 + px0 + 1];
            float v2 = t[r * 35 + px0 + 2];
            float v3 = t[r * 35 + px0 + 3];
            float2 W0 = W[r * 3 + 0];
            float2 W1 = W[r * 3 + 1];
            float2 W2 = W[r * 3 + 2];
            cA0 = fmaf(v0, W0.x, cA0);  cA1 = fmaf(v0, W0.y, cA1);
            cA0 = fmaf(v1, W1.x, cA0);  cA1 = fmaf(v1, W1.y, cA1);
            cA0 = fmaf(v2, W2.x, cA0);  cA1 = fmaf(v2, W2.y, cA1);
            cB0 = fmaf(v1, W0.x, cB0);  cB1 = fmaf(v1, W0.y, cB1);
            cB0 = fmaf(v2, W1.x, cB0);  cB1 = fmaf(v2, W1.y, cB1);
            cB0 = fmaf(v3, W2.x, cB0);  cB1 = fmaf(v3, W2.y, cB1);
        }
    }

    // ---- Channel values + one fused 10-value butterfly --------------------
    float xa0 = tile[lane][36 + px0];
    float xa1 = tile[lane + 32][36 + px0];
    float xb0 = tile[lane][36 + px1];
    float xb1 = tile[lane + 32][36 + px1];

    float ssA = xa0 + xa1;
    float saA = fabsf(xa0) + fabsf(xa1);
    float smA = fmaxf(fabsf(xa0), fabsf(xa1));
    float ssB = xb0 + xb1;
    float saB = fabsf(xb0) + fabsf(xb1);
    float smB = fmaxf(fabsf(xb0), fabsf(xb1));
    #pragma unroll
    for (int o = 16; o > 0; o >>= 1) {
        cA0 += __shfl_xor_sync(0xffffffffu, cA0, o);
        cA1 += __shfl_xor_sync(0xffffffffu, cA1, o);
        cB0 += __shfl_xor_sync(0xffffffffu, cB0, o);
        cB1 += __shfl_xor_sync(0xffffffffu, cB1, o);
        ssA += __shfl_xor_sync(0xffffffffu, ssA, o);
        saA += __shfl_xor_sync(0xffffffffu, saA, o);
        smA  = fmaxf(smA, __shfl_xor_sync(0xffffffffu, smA, o));
        ssB += __shfl_xor_sync(0xffffffffu, ssB, o);
        saB += __shfl_xor_sync(0xffffffffu, saB, o);
        smB  = fmaxf(smB, __shfl_xor_sync(0xffffffffu, smB, o));
    }

    float alA = MAXR * tanh_exp(cA0 + b0);
    float beA = MAXR * tanh_exp(cA1 + b1);
    float alB = MAXR * tanh_exp(cB0 + b0);
    float beB = MAXR * tanh_exp(cB1 + b1);

    // ---- Screen C0 per pixel ----------------------------------------------
    bool okA = fabsf(alA) * (fabsf(beA) * (saA * (1.0f / 64.0f)) - smA) >= 101.0f;
    bool okB = fabsf(alB) * (fabsf(beB) * (saB * (1.0f / 64.0f)) - smB) >= 101.0f;
    if (lane == 0) {
        if (okA) out[p0 + px0] = ssA * (1.0f / 64.0f);
        if (okB) out[p0 + px1] = ssB * (1.0f / 64.0f);
    }
    if (okA && okB) return;

    // ---- Exact path(s) (rare): full tanh interaction + softmax ------------
    #pragma unroll
    for (int p = 0; p < 2; p++) {
        bool ok      = p ? okB : okA;
        if (ok) continue;
        float alpha  = p ? alB : alA;
        float beta   = p ? beB : beA;
        float xj0    = p ? xb0 : xa0;
        float xj1    = p ? xb1 : xa1;
        int   px     = p ? px1 : px0;

        float ab  = alpha * beta;
        float nc0 = -alpha * xj0;
        float nc1 = -alpha * xj1;
        const float* xc = &tile[0][36 + px];

        float acc0 = 0.0f, acc1 = 0.0f;
        #pragma unroll 8
        for (int i = 0; i < 64; i++) {
            float xi = xc[i * 105];     // LDS broadcast
            float z0 = fmaf(ab, xi, nc0);
            float z1 = fmaf(ab, xi, nc1);
            acc0 = fmaf(z0, tanh_fast(z0), acc0);
            acc1 = fmaf(z1, tanh_fast(z1), acc1);
        }

        float l0 = fminf(fmaxf(acc0 * (-1.0f / 64.0f), -MAXR), MAXR);
        float l1 = fminf(fmaxf(acc1 * (-1.0f / 64.0f), -MAXR), MAXR);

        float m = fmaxf(l0, l1);
        #pragma unroll
        for (int o = 16; o > 0; o >>= 1)
            m = fmaxf(m, __shfl_xor_sync(0xffffffffu, m, o));

        float e0 = __expf(l0 - m);
        float e1 = __expf(l1 - m);
        float num = fmaf(xj0, e0, xj1 * e1);
        float den = e0 + e1;
        #pragma unroll
        for (int o = 16; o > 0; o >>= 1) {
            num += __shfl_xor_sync(0xffffffffu, num, o);
            den += __shfl_xor_sync(0xffffffffu, den, o);
        }

        if (lane == 0) out[p0 + px] = num / den;
    }
}

extern "C" void kernel_launch(void* const* d_in, const int* in_sizes, int n_in,
                              void* d_out, int out_size) {
    const float* x    = (const float*)d_in[0];
    const float* w    = (const float*)d_in[1];
    const float* bias = (const float*)d_in[2];
    float* out        = (float*)d_out;

    dsf_fused_kernel<<<512, 512>>>(x, w, bias, out);
}

// round 11
// speedup vs baseline: 1.3200x; 1.1575x over previous
#include <cuda_runtime.h>

#define MAXR 100.0f

__device__ __forceinline__ float tanh_fast(float x) {
    float r;
    asm("tanh.approx.f32 %0, %1;" : "=f"(r) : "f"(x));
    return r;
}

// Accurate fast tanh: 1 - 2/(1+e^{2s}).  ~1e-7 abs err. Saturates correctly.
__device__ __forceinline__ float tanh_exp(float s) {
    float e2 = __expf(2.0f * s);
    return 1.0f - __fdividef(2.0f, 1.0f + e2);
}

// Parity-folded warp reduction: even lanes end up with the full 32-lane
// reduction of `va`, odd lanes with that of `vb`. 5 shfl instead of 10.
__device__ __forceinline__ float fold_add(float va, float vb, int bit) {
    float send = bit ? va : vb;
    float keep = bit ? vb : va;
    float r = keep + __shfl_xor_sync(0xffffffffu, send, 1);
    #pragma unroll
    for (int o = 2; o < 32; o <<= 1)
        r += __shfl_xor_sync(0xffffffffu, r, o);
    return r;
}
__device__ __forceinline__ float fold_max(float va, float vb, int bit) {
    float send = bit ? va : vb;
    float keep = bit ? vb : va;
    float r = fmaxf(keep, __shfl_xor_sync(0xffffffffu, send, 1));
    #pragma unroll
    for (int o = 2; o < 32; o <<= 1)
        r = fmaxf(r, __shfl_xor_sync(0xffffffffu, r, o));
    return r;
}

// ---------------------------------------------------------------------------
// Per block = 32 consecutive same-row pixels (half image row), 512 threads,
// 16 warps x 2 pixels/warp. Grid 512 -> ONE wave at occupancy 4.
// Tile layout: tile[c*110 + r*36 + col], col 0 = left halo, 1..32 = centers,
// 33 = right halo. c*110 + r*36 + even  => conv taps readable as LDS.64;
// 110/2 = 55 odd => conflict-free 64-bit lane access.
// Reductions parity-folded: even lanes finish pixel A, odd lanes pixel B;
// epilogue (tanh, screen) computed once per parity instead of duplicated.
// Screen C0: logit_j = -|a|*mean_i(|d|*tanh(|a d|)) <= 0 clipped at -100;
//   |a|*(|b|*mean|x| - max|x|) >= 101 ==> all logits clip -> softmax uniform
//   -> out = mean_c(x). Fallback: exact tanh path (rare).
// ---------------------------------------------------------------------------
__global__ __launch_bounds__(512, 4) void dsf_fused_kernel(
    const float* __restrict__ x,
    const float* __restrict__ wgt,
    const float* __restrict__ bias,
    float* __restrict__ out) {

    __shared__ float  tile[64 * 110];   // 28.2 KB
    __shared__ float2 sw2[576];         // (w_out0, w_out1) per [c][tap]

    int tid = threadIdx.x;
    int p0  = blockIdx.x * 32;
    int b   = p0 >> 12;
    int hw0 = p0 & 4095;
    int h   = hw0 >> 6;
    int w0  = hw0 & 63;                 // 0 or 32 -> float4 aligned
    const float* xb = x + b * 262144;

    // ---- Phase 1a: halo tile, 1536 items = (c, r, f), exactly 3/thread ----
    #pragma unroll
    for (int k = 0; k < 3; k++) {
        int q  = tid + k * 512;
        int c  = q / 24;
        int rm = q - c * 24;
        int r  = rm >> 3;
        int f  = rm & 7;
        int hh = h + r - 1;
        bool rowok = (unsigned)hh < 64u;
        const float* src = xb + c * 4096 + hh * 64;

        float4 v = make_float4(0.f, 0.f, 0.f, 0.f);
        if (rowok)
            v = *reinterpret_cast<const float4*>(src + w0 + f * 4);
        float* d = &tile[c * 110 + r * 36 + 1 + f * 4];
        d[0] = v.x; d[1] = v.y; d[2] = v.z; d[3] = v.w;

        if (f == 0) {
            float hv = 0.0f;
            if (rowok && w0 > 0) hv = src[w0 - 1];
            tile[c * 110 + r * 36] = hv;
        } else if (f == 7) {
            float hv = 0.0f;
            if (rowok && w0 + 32 < 64) hv = src[w0 + 32];
            tile[c * 110 + r * 36 + 33] = hv;
        }
    }
    // ---- Phase 1b: weights -> (o0,o1) float2 pairs ------------------------
    if (tid < 144) {
        const float4* gw = reinterpret_cast<const float4*>(wgt);
        float4 wa = gw[tid];            // out0 floats
        float4 wb = gw[144 + tid];      // out1 floats
        int e = tid * 4;
        sw2[e + 0] = make_float2(wa.x, wb.x);
        sw2[e + 1] = make_float2(wa.y, wb.y);
        sw2[e + 2] = make_float2(wa.z, wb.z);
        sw2[e + 3] = make_float2(wa.w, wb.w);
    }
    float b0 = __ldg(&bias[0]);
    float b1 = __ldg(&bias[1]);
    __syncthreads();

    int wid    = tid >> 5;              // warp -> pixels 2w, 2w+1
    int lane   = tid & 31;
    int parity = lane & 1;              // 0 -> pixel A, 1 -> pixel B
    int px0    = wid * 2;

    // ---- Phase 2: conv for BOTH pixels (shared window + weights) ----------
    float cA0 = 0.f, cA1 = 0.f, cB0 = 0.f, cB1 = 0.f;
    #pragma unroll
    for (int g = 0; g < 2; g++) {
        int c = lane + g * 32;
        const float*  t = &tile[c * 110];
        const float2* W = &sw2[c * 9];
        #pragma unroll
        for (int r = 0; r < 3; r++) {
            float2 p01 = *reinterpret_cast<const float2*>(&t[r * 36 + px0]);
            float2 p23 = *reinterpret_cast<const float2*>(&t[r * 36 + px0 + 2]);
            float2 W0 = W[r * 3 + 0];
            float2 W1 = W[r * 3 + 1];
            float2 W2 = W[r * 3 + 2];
            cA0 = fmaf(p01.x, W0.x, cA0);  cA1 = fmaf(p01.x, W0.y, cA1);
            cA0 = fmaf(p01.y, W1.x, cA0);  cA1 = fmaf(p01.y, W1.y, cA1);
            cA0 = fmaf(p23.x, W2.x, cA0);  cA1 = fmaf(p23.x, W2.y, cA1);
            cB0 = fmaf(p01.y, W0.x, cB0);  cB1 = fmaf(p01.y, W0.y, cB1);
            cB0 = fmaf(p23.x, W1.x, cB0);  cB1 = fmaf(p23.x, W1.y, cB1);
            cB0 = fmaf(p23.y, W2.x, cB0);  cB1 = fmaf(p23.y, W2.y, cB1);
        }
    }

    // ---- Channel values + parity-folded reductions ------------------------
    // Center col of pixel px = px + 1.
    float xa0 = tile[lane * 110 + 37 + px0];         // pixel A, ch lane
    float xa1 = tile[(lane + 32) * 110 + 37 + px0];  // pixel A, ch lane+32
    float xb0 = tile[lane * 110 + 38 + px0];         // pixel B
    float xb1 = tile[(lane + 32) * 110 + 38 + px0];

    float ss = fold_add(xa0 + xa1, xb0 + xb1, parity);
    float sa = fold_add(fabsf(xa0) + fabsf(xa1), fabsf(xb0) + fabsf(xb1), parity);
    float sm = fold_max(fmaxf(fabsf(xa0), fabsf(xa1)),
                        fmaxf(fabsf(xb0), fabsf(xb1)), parity);
    float c0 = fold_add(cA0, cB0, parity);
    float c1 = fold_add(cA1, cB1, parity);

    // Per-parity epilogue: even lanes hold pixel A scalars, odd pixel B.
    float alpha = MAXR * tanh_exp(c0 + b0);
    float beta  = MAXR * tanh_exp(c1 + b1);

    // ---- Screen C0 ---------------------------------------------------------
    bool ok = fabsf(alpha) * (fabsf(beta) * (sa * (1.0f / 64.0f)) - sm) >= 101.0f;
    if (lane < 2 && ok) out[p0 + px0 + lane] = ss * (1.0f / 64.0f);
    if (__all_sync(0xffffffffu, ok)) return;

    // ---- Exact path(s) (rare): full tanh interaction + softmax ------------
    #pragma unroll
    for (int p = 0; p < 2; p++) {
        if (__shfl_sync(0xffffffffu, (int)ok, p)) continue;
        float alpha_p = __shfl_sync(0xffffffffu, alpha, p);
        float beta_p  = __shfl_sync(0xffffffffu, beta, p);
        float xj0 = p ? xb0 : xa0;
        float xj1 = p ? xb1 : xa1;
        int   px  = px0 + p;

        float ab  = alpha_p * beta_p;
        float nc0 = -alpha_p * xj0;
        float nc1 = -alpha_p * xj1;
        const float* xc = &tile[37 + px];

        float acc0 = 0.0f, acc1 = 0.0f;
        #pragma unroll 8
        for (int i = 0; i < 64; i++) {
            float xi = xc[i * 110];     // LDS broadcast
            float z0 = fmaf(ab, xi, nc0);
            float z1 = fmaf(ab, xi, nc1);
            acc0 = fmaf(z0, tanh_fast(z0), acc0);
            acc1 = fmaf(z1, tanh_fast(z1), acc1);
        }

        float l0 = fminf(fmaxf(acc0 * (-1.0f / 64.0f), -MAXR), MAXR);
        float l1 = fminf(fmaxf(acc1 * (-1.0f / 64.0f), -MAXR), MAXR);

        float m = fmaxf(l0, l1);
        #pragma unroll
        for (int o = 16; o > 0; o >>= 1)
            m = fmaxf(m, __shfl_xor_sync(0xffffffffu, m, o));

        float e0 = __expf(l0 - m);
        float e1 = __expf(l1 - m);
        float num = fmaf(xj0, e0, xj1 * e1);
        float den = e0 + e1;
        #pragma unroll
        for (int o = 16; o > 0; o >>= 1) {
            num += __shfl_xor_sync(0xffffffffu, num, o);
            den += __shfl_xor_sync(0xffffffffu, den, o);
        }

        if (lane == 0) out[p0 + px] = num / den;
    }
}

extern "C" void kernel_launch(void* const* d_in, const int* in_sizes, int n_in,
                              void* d_out, int out_size) {
    const float* x    = (const float*)d_in[0];
    const float* w    = (const float*)d_in[1];
    const float* bias = (const float*)d_in[2];
    float* out        = (float*)d_out;

    dsf_fused_kernel<<<512, 512>>>(x, w, bias, out);
}